// round 10
// baseline (speedup 1.0000x reference)
#include <cuda_runtime.h>
#include <cuda_fp16.h>
#include <cstdint>

#define TT 2048
#define NN 64
#define EE 1024
#define DD 1024
#define AA 512
#define TCH 16

#define NIT 32      // K=32 per iteration

// ---------------- device scratch ----------------
__device__ float g_scoresP[2 * NN * TT];   // [half][n][t]
__device__ float g_alphaT[NN * TT];
__device__ float g_part[TCH * NN * EE];
__device__ float g_dproj[NN * AA];         // [n][a] fp32, exact
__device__ __align__(16) __half g_W16[64 * 2 * AA * 8];  // [s][chunk][a][8]

// ---------------- helpers ----------------
__device__ __forceinline__ uint32_t smem_u32(const void* p) {
    uint32_t a;
    asm("{ .reg .u64 t; cvta.to.shared.u64 t, %1; cvt.u32.u64 %0, t; }" : "=r"(a) : "l"(p));
    return a;
}
__device__ __forceinline__ void ldmx4(uint32_t* r, uint32_t a) {
    asm volatile("ldmatrix.sync.aligned.m8n8.x4.shared.b16 {%0,%1,%2,%3}, [%4];"
                 : "=r"(r[0]), "=r"(r[1]), "=r"(r[2]), "=r"(r[3]) : "r"(a));
}
__device__ __forceinline__ void mma16816(float* d, const uint32_t* a, uint32_t b0, uint32_t b1) {
    asm volatile(
        "mma.sync.aligned.m16n8k16.row.col.f32.f16.f16.f32 "
        "{%0,%1,%2,%3}, {%4,%5,%6,%7}, {%8,%9}, {%0,%1,%2,%3};"
        : "+f"(d[0]), "+f"(d[1]), "+f"(d[2]), "+f"(d[3])
        : "r"(a[0]), "r"(a[1]), "r"(a[2]), "r"(a[3]), "r"(b0), "r"(b1));
}
__device__ __forceinline__ void cp16(uint32_t dst, const void* src) {
    asm volatile("cp.async.cg.shared.global [%0], [%1], 16;" :: "r"(dst), "l"(src) : "memory");
}
__device__ __forceinline__ void cp_commit() { asm volatile("cp.async.commit_group;" ::: "memory"); }
__device__ __forceinline__ void cp_wait0()  { asm volatile("cp.async.wait_group 0;" ::: "memory"); }
__device__ __forceinline__ float tanh_fast(float x) {
    float e = __expf(2.0f * x);
    return 1.0f - __fdividef(2.0f, e + 1.0f);
}

// ---------------- smem layout (bytes), 48KB total ----------------
// A buf: [panel(2)][chunk(2)][row(128)][16B] = 8KB ; addr = p*4096 + c*2048 + r*16
#define A_OFF(buf)  ((uint32_t)((buf) * 8192))
// W buf: [panel(2)][chunk(2)][row(256)][16B] = 16KB ; addr = p*8192 + c*4096 + r*16
#define W_OFF(buf)  ((uint32_t)(16384 + (buf) * 16384))
#define RED_OFF 0u
#define SMEMSZ  49152

// ---------------------------------------------------------------------------
// fused prep: blocks [0,1024) -> W_e fp16 plane layout; [1024,1088) -> dproj
// ---------------------------------------------------------------------------
__global__ __launch_bounds__(512) void prep_kernel(const float* __restrict__ We,
                                                   const float* __restrict__ dec_h,
                                                   const float* __restrict__ W_d) {
    if (blockIdx.x < 1024) {
        int i = blockIdx.x * 512 + threadIdx.x;
        int a = i >> 10, e = i & 1023;
        int s = e >> 4, c = (e >> 3) & 1, kk = e & 7;
        g_W16[(((size_t)s * 2 + c) * AA + a) * 8 + kk] = __float2half(We[i]);
    } else {
        __shared__ float dsh[DD];
        const int n = blockIdx.x - 1024, a = threadIdx.x;
        for (int k = a; k < DD; k += 512) dsh[k] = dec_h[(size_t)n * DD + k];
        __syncthreads();
        const float4* wd = (const float4*)(W_d + (size_t)a * DD);
        float acc = 0.f;
        #pragma unroll 8
        for (int k4 = 0; k4 < DD / 4; k4++) {
            float4 w = wd[k4];
            acc += w.x * dsh[k4 * 4] + w.y * dsh[k4 * 4 + 1] +
                   w.z * dsh[k4 * 4 + 2] + w.w * dsh[k4 * 4 + 3];
        }
        g_dproj[n * AA + a] = acc;
    }
}

// ---------------------------------------------------------------------------
// scores: block = (t-pair, a-half). M=128 (2t x 64n), N=256 (a-half), K=32/iter.
// 512 threads, 16 warps, warp-tile 64x32. Conflict-free plane smem layout.
// ---------------------------------------------------------------------------
__global__ __launch_bounds__(512, 1) void scores_mma_kernel(
    const float* __restrict__ enc, const float* __restrict__ v) {
    extern __shared__ char smem[];
    const uint32_t sb = smem_u32(smem);
    const int tid = threadIdx.x;
    const int tile = blockIdx.x >> 1;       // t-pair (0..1023)
    const int half = blockIdx.x & 1;        // a-half
    const int lane = tid & 31;
    const int wid = tid >> 5;               // 0..15
    const int mh = wid >> 3;                // m-half
    const int ng = wid & 7;                 // n-group (32 cols)
    const int row = tid >> 2;               // A loader row 0..127
    const int k4 = (tid & 3) * 4;           // A loader k offset in panel
    const int aBase = half * 256;

    const size_t rowBase = ((size_t)tile * 128 + row) * EE;

    float c[4][4][4] = {};

    // W copy: thread -> (panel wp, row wr); copies both chunks
    const int wp = tid >> 8;
    const int wr = tid & 255;
    auto cpW = [&](int i, int b) {
        const int s = 2 * i + wp;
        uint32_t dst = sb + W_OFF(b) + (uint32_t)wp * 8192 + (uint32_t)wr * 16;
        cp16(dst,        g_W16 + (((size_t)s * 2 + 0) * AA + aBase + wr) * 8);
        cp16(dst + 4096, g_W16 + (((size_t)s * 2 + 1) * AA + aBase + wr) * 8);
    };

    // A store: packed fp16 convert, 8B per panel into plane layout
    const uint32_t aStoreOff = (uint32_t)((k4 >> 3) * 2048 + row * 16 + (k4 & 7) * 2);
    auto stsA = [&](int b, float4 x0, float4 x1) {
        __half2 h0a = __floats2half2_rn(x0.x, x0.y);
        __half2 h0b = __floats2half2_rn(x0.z, x0.w);
        __half2 h1a = __floats2half2_rn(x1.x, x1.y);
        __half2 h1b = __floats2half2_rn(x1.z, x1.w);
        uint2 p0, p1;
        p0.x = *(uint32_t*)&h0a; p0.y = *(uint32_t*)&h0b;
        p1.x = *(uint32_t*)&h1a; p1.y = *(uint32_t*)&h1b;
        *(uint2*)(smem + A_OFF(b) + aStoreOff) = p0;            // panel 0
        *(uint2*)(smem + A_OFF(b) + 4096 + aStoreOff) = p1;     // panel 1
    };

    // ldmatrix address components (plane layout, conflict-free: 16B row stride)
    const uint32_t aRowOff = (uint32_t)(lane >> 4) * 2048 +
                             (uint32_t)(mh * 64 + (lane & 15)) * 16;
    const uint32_t bRowOff = (uint32_t)((lane >> 3) & 1) * 4096 +
                             (uint32_t)(ng * 32 + (lane >> 4) * 8 + (lane & 7)) * 16;

    // ---- prologue ----
    cpW(0, 0); cp_commit();
    float4 x0 = *(const float4*)(enc + rowBase + k4);
    float4 x1 = *(const float4*)(enc + rowBase + 16 + k4);

    #pragma unroll 1
    for (int i = 0; i < NIT; i++) {
        const int b = i & 1;
        stsA(b, x0, x1);
        cp_wait0();        // this thread's W(i) copies done
        __syncthreads();   // everyone's W(i) + A stores visible
        if (i + 1 < NIT) {
            x0 = *(const float4*)(enc + rowBase + (size_t)(i + 1) * 32 + k4);
            x1 = *(const float4*)(enc + rowBase + (size_t)(i + 1) * 32 + 16 + k4);
            cpW(i + 1, b ^ 1);
            cp_commit();
        }

        #pragma unroll
        for (int p = 0; p < 2; p++) {
            uint32_t aH[4][4];
            #pragma unroll
            for (int mi = 0; mi < 4; mi++)
                ldmx4(aH[mi], sb + A_OFF(b) + (uint32_t)p * 4096 + (uint32_t)mi * 256 + aRowOff);
            uint32_t bb[2][4];   // [ntp]: r0,r1 = nt even, r2,r3 = nt odd
            #pragma unroll
            for (int ntp = 0; ntp < 2; ntp++)
                ldmx4(bb[ntp], sb + W_OFF(b) + (uint32_t)p * 8192 + (uint32_t)ntp * 256 + bRowOff);
            #pragma unroll
            for (int nt = 0; nt < 4; nt++) {
                const uint32_t b0 = bb[nt >> 1][(nt & 1) * 2];
                const uint32_t b1 = bb[nt >> 1][(nt & 1) * 2 + 1];
                #pragma unroll
                for (int mi = 0; mi < 4; mi++)
                    mma16816(c[mi][nt], aH[mi], b0, b1);
            }
        }
    }

    // ---- epilogue: + dproj (exact fp32), tanh, dot v, reduce ----
    const int g = lane >> 2, t4 = lane & 3;
    float p[8];
    #pragma unroll
    for (int i = 0; i < 8; i++) p[i] = 0.f;

    #pragma unroll
    for (int nt = 0; nt < 4; nt++) {
        const int a0 = aBase + ng * 32 + nt * 8 + t4 * 2;
        const float v0 = __ldg(v + a0), v1 = __ldg(v + a0 + 1);
        #pragma unroll
        for (int mi = 0; mi < 4; mi++) {
            const int n0 = mi * 16 + g;
            float2 d0 = *(const float2*)(g_dproj + (size_t)n0 * AA + a0);
            float2 d1 = *(const float2*)(g_dproj + (size_t)(n0 + 8) * AA + a0);
            p[mi * 2 + 0] += tanh_fast(c[mi][nt][0] + d0.x) * v0 +
                             tanh_fast(c[mi][nt][1] + d0.y) * v1;
            p[mi * 2 + 1] += tanh_fast(c[mi][nt][2] + d1.x) * v0 +
                             tanh_fast(c[mi][nt][3] + d1.y) * v1;
        }
    }
    #pragma unroll
    for (int i = 0; i < 8; i++) {
        p[i] += __shfl_down_sync(0xffffffffu, p[i], 1);
        p[i] += __shfl_down_sync(0xffffffffu, p[i], 2);
    }
    float* red = (float*)(smem + RED_OFF);   // [128][8], reuses A region
    __syncthreads();
    if (t4 == 0) {
        #pragma unroll
        for (int mi = 0; mi < 4; mi++) {
            int r0 = mh * 64 + mi * 16 + g;
            red[r0 * 8 + ng] = p[mi * 2 + 0];
            red[(r0 + 8) * 8 + ng] = p[mi * 2 + 1];
        }
    }
    __syncthreads();
    if (tid < 128) {
        float s = 0.f;
        #pragma unroll
        for (int w = 0; w < 8; w++) s += red[tid * 8 + w];
        int t = tile * 2 + (tid >> 6);
        int n = tid & 63;
        g_scoresP[(size_t)half * (NN * TT) + (size_t)n * TT + t] = s;
    }
}

// ---------------------------------------------------------------------------
// softmax over T per column n — 512 threads, one float4 per thread
// ---------------------------------------------------------------------------
__global__ __launch_bounds__(512) void softmax_kernel(float* __restrict__ out_alpha) {
    const int n = blockIdx.x, tid = threadIdx.x;
    const int lane = tid & 31, w = tid >> 5;
    __shared__ float sm[16];
    const float* s0 = g_scoresP + (size_t)n * TT;
    const float* s1 = g_scoresP + (size_t)NN * TT + (size_t)n * TT;

    float4 a4 = *(const float4*)(s0 + tid * 4);
    float4 b4 = *(const float4*)(s1 + tid * 4);
    float s[4] = {a4.x + b4.x, a4.y + b4.y, a4.z + b4.z, a4.w + b4.w};

    float m = fmaxf(fmaxf(s[0], s[1]), fmaxf(s[2], s[3]));
    #pragma unroll
    for (int o = 16; o; o >>= 1) m = fmaxf(m, __shfl_xor_sync(0xffffffffu, m, o));
    if (lane == 0) sm[w] = m;
    __syncthreads();
    if (w == 0) {
        float t = sm[lane & 15];
        #pragma unroll
        for (int o = 8; o; o >>= 1) t = fmaxf(t, __shfl_xor_sync(0xffffffffu, t, o));
        sm[lane & 15] = t;
    }
    __syncthreads();
    m = sm[0];

    float e[4], acc = 0.f;
    #pragma unroll
    for (int i = 0; i < 4; i++) { e[i] = expf(s[i] - m); acc += e[i]; }
    #pragma unroll
    for (int o = 16; o; o >>= 1) acc += __shfl_xor_sync(0xffffffffu, acc, o);
    __syncthreads();
    if (lane == 0) sm[w] = acc;
    __syncthreads();
    if (w == 0) {
        float t = sm[lane & 15];
        #pragma unroll
        for (int o = 8; o; o >>= 1) t += __shfl_xor_sync(0xffffffffu, t, o);
        sm[lane & 15] = t;
    }
    __syncthreads();
    const float inv = 1.0f / sm[0];

    float4 al;
    al.x = e[0] * inv; al.y = e[1] * inv; al.z = e[2] * inv; al.w = e[3] * inv;
    *(float4*)(g_alphaT + (size_t)n * TT + tid * 4) = al;
    const int t0 = tid * 4;
    out_alpha[(size_t)(t0 + 0) * NN + n] = al.x;
    out_alpha[(size_t)(t0 + 1) * NN + n] = al.y;
    out_alpha[(size_t)(t0 + 2) * NN + n] = al.z;
    out_alpha[(size_t)(t0 + 3) * NN + n] = al.w;
}

// ---------------------------------------------------------------------------
// ctx = alpha^T * enc  (partials + reduce) — at DRAM roofline already
// ---------------------------------------------------------------------------
__global__ __launch_bounds__(256) void ctx_partial_kernel(const float* __restrict__ enc) {
    const int tc = blockIdx.x & (TCH - 1);
    const int n = blockIdx.x / TCH;
    const int e0 = threadIdx.x * 4;
    float4 acc = make_float4(0.f, 0.f, 0.f, 0.f);
    const int tBeg = tc * (TT / TCH);
    #pragma unroll 4
    for (int t = tBeg; t < tBeg + TT / TCH; ++t) {
        float al = g_alphaT[(size_t)n * TT + t];
        float4 ev = *(const float4*)(enc + ((size_t)t * NN + n) * EE + e0);
        acc.x += al * ev.x; acc.y += al * ev.y;
        acc.z += al * ev.z; acc.w += al * ev.w;
    }
    *(float4*)&g_part[((size_t)tc * NN + n) * EE + e0] = acc;
}

__global__ void ctx_reduce_kernel(float* __restrict__ out_ctx) {
    const int n = blockIdx.x;
    const int e0 = threadIdx.x * 4;
    float4 acc = make_float4(0.f, 0.f, 0.f, 0.f);
    #pragma unroll
    for (int tc = 0; tc < TCH; ++tc) {
        float4 p = *(const float4*)&g_part[((size_t)tc * NN + n) * EE + e0];
        acc.x += p.x; acc.y += p.y; acc.z += p.z; acc.w += p.w;
    }
    *(float4*)&out_ctx[(size_t)n * EE + e0] = acc;
}

// ---------------------------------------------------------------------------
extern "C" void kernel_launch(void* const* d_in, const int* in_sizes, int n_in,
                              void* d_out, int out_size) {
    const float* enc = (const float*)d_in[0];   // [T, N, E]
    const float* dec = (const float*)d_in[1];   // [N, D]
    const float* We  = (const float*)d_in[2];   // [A, E]
    const float* Wd  = (const float*)d_in[3];   // [A, D]
    const float* v   = (const float*)d_in[4];   // [1, A]

    float* out = (float*)d_out;
    float* out_ctx = out;                 // [N, E]
    float* out_alpha = out + NN * EE;     // [T, N]

    prep_kernel<<<1088, 512>>>(We, dec, Wd);
    scores_mma_kernel<<<TT, 512, SMEMSZ>>>(enc, v);
    softmax_kernel<<<NN, 512>>>(out_alpha);
    ctx_partial_kernel<<<NN * TCH, 256>>>(enc);
    ctx_reduce_kernel<<<NN, 256>>>(out_ctx);
}

// round 11
// speedup vs baseline: 1.1063x; 1.1063x over previous
#include <cuda_runtime.h>
#include <cuda_fp16.h>
#include <cstdint>

#define TT 2048
#define NN 64
#define EE 1024
#define DD 1024
#define AA 512
#define TCH 16

#define NIT 32      // K=32 per iteration

// ---------------- device scratch ----------------
__device__ float g_scoresP[2 * NN * TT];   // [half][n][t]
__device__ float g_alphaT[NN * TT];
__device__ float g_part[TCH * NN * EE];
__device__ float g_dproj[NN * AA];         // [n][a] fp32, exact
__device__ __align__(16) __half g_W16[64 * 2 * AA * 8];  // [s][chunk][a][8]

// ---------------- helpers ----------------
__device__ __forceinline__ uint32_t smem_u32(const void* p) {
    uint32_t a;
    asm("{ .reg .u64 t; cvta.to.shared.u64 t, %1; cvt.u32.u64 %0, t; }" : "=r"(a) : "l"(p));
    return a;
}
__device__ __forceinline__ void ldmx4(uint32_t* r, uint32_t a) {
    asm volatile("ldmatrix.sync.aligned.m8n8.x4.shared.b16 {%0,%1,%2,%3}, [%4];"
                 : "=r"(r[0]), "=r"(r[1]), "=r"(r[2]), "=r"(r[3]) : "r"(a));
}
__device__ __forceinline__ void mma16816(float* d, const uint32_t* a, uint32_t b0, uint32_t b1) {
    asm volatile(
        "mma.sync.aligned.m16n8k16.row.col.f32.f16.f16.f32 "
        "{%0,%1,%2,%3}, {%4,%5,%6,%7}, {%8,%9}, {%0,%1,%2,%3};"
        : "+f"(d[0]), "+f"(d[1]), "+f"(d[2]), "+f"(d[3])
        : "r"(a[0]), "r"(a[1]), "r"(a[2]), "r"(a[3]), "r"(b0), "r"(b1));
}
__device__ __forceinline__ void cp16(uint32_t dst, const void* src) {
    asm volatile("cp.async.cg.shared.global [%0], [%1], 16;" :: "r"(dst), "l"(src) : "memory");
}
__device__ __forceinline__ void cp_commit() { asm volatile("cp.async.commit_group;" ::: "memory"); }
__device__ __forceinline__ void cp_wait0()  { asm volatile("cp.async.wait_group 0;" ::: "memory"); }
__device__ __forceinline__ float tanh_fast(float x) {
    float e = __expf(2.0f * x);
    return 1.0f - __fdividef(2.0f, e + 1.0f);
}

// ---------------- smem layout (bytes), 48KB total ----------------
// A buf: [panel(2)][chunk(2)][row(128)][16B] = 8KB ; addr = p*4096 + c*2048 + r*16
#define A_OFF(buf)  ((uint32_t)((buf) * 8192))
// W buf: [panel(2)][chunk(2)][row(256)][16B] = 16KB ; addr = p*8192 + c*4096 + r*16
#define W_OFF(buf)  ((uint32_t)(16384 + (buf) * 16384))
#define RED_OFF 0u
#define SMEMSZ  49152

// ---------------------------------------------------------------------------
// prep: fp16 of W_e, plane layout [s][chunk][a][8]
// ---------------------------------------------------------------------------
__global__ void prepW_kernel(const float* __restrict__ We) {
    int i = blockIdx.x * blockDim.x + threadIdx.x;
    if (i >= AA * EE) return;
    int a = i >> 10, e = i & 1023;
    int s = e >> 4, c = (e >> 3) & 1, kk = e & 7;
    g_W16[(((size_t)s * 2 + c) * AA + a) * 8 + kk] = __float2half(We[i]);
}

// ---------------------------------------------------------------------------
// dproj[n][a] = dec_h[n]·W_d[a]  (exact fp32). Block per n, thread per a.
// ---------------------------------------------------------------------------
__global__ __launch_bounds__(512) void dproj_kernel(const float* __restrict__ dec_h,
                                                    const float* __restrict__ W_d) {
    __shared__ float dsh[DD];
    const int n = blockIdx.x, a = threadIdx.x;
    for (int k = a; k < DD; k += 512) dsh[k] = dec_h[(size_t)n * DD + k];
    __syncthreads();
    const float4* wd = (const float4*)(W_d + (size_t)a * DD);
    float acc = 0.f;
    #pragma unroll 8
    for (int k4 = 0; k4 < DD / 4; k4++) {
        float4 w = wd[k4];
        acc += w.x * dsh[k4 * 4] + w.y * dsh[k4 * 4 + 1] +
               w.z * dsh[k4 * 4 + 2] + w.w * dsh[k4 * 4 + 3];
    }
    g_dproj[n * AA + a] = acc;
}

// ---------------------------------------------------------------------------
// scores: block = (t-pair, a-half). M=128 (2t x 64n), N=256 (a-half), K=32/iter.
// 512 threads, 16 warps, warp-tile 64x32. Conflict-free plane smem layout.
// ---------------------------------------------------------------------------
__global__ __launch_bounds__(512, 1) void scores_mma_kernel(
    const float* __restrict__ enc, const float* __restrict__ v) {
    extern __shared__ char smem[];
    const uint32_t sb = smem_u32(smem);
    const int tid = threadIdx.x;
    const int tile = blockIdx.x >> 1;       // t-pair (0..1023)
    const int half = blockIdx.x & 1;        // a-half
    const int lane = tid & 31;
    const int wid = tid >> 5;               // 0..15
    const int mh = wid >> 3;                // m-half
    const int ng = wid & 7;                 // n-group (32 cols)
    const int row = tid >> 2;               // A loader row 0..127
    const int k4 = (tid & 3) * 4;           // A loader k offset in panel
    const int aBase = half * 256;

    const size_t rowBase = ((size_t)tile * 128 + row) * EE;

    float c[4][4][4] = {};

    // W copy: thread -> (panel wp, row wr); copies both chunks
    const int wp = tid >> 8;
    const int wr = tid & 255;
    auto cpW = [&](int i, int b) {
        const int s = 2 * i + wp;
        uint32_t dst = sb + W_OFF(b) + (uint32_t)wp * 8192 + (uint32_t)wr * 16;
        cp16(dst,        g_W16 + (((size_t)s * 2 + 0) * AA + aBase + wr) * 8);
        cp16(dst + 4096, g_W16 + (((size_t)s * 2 + 1) * AA + aBase + wr) * 8);
    };

    // A store: packed fp16 convert, 8B per panel into plane layout
    const uint32_t aStoreOff = (uint32_t)((k4 >> 3) * 2048 + row * 16 + (k4 & 7) * 2);
    auto stsA = [&](int b, float4 x0, float4 x1) {
        __half2 h0a = __floats2half2_rn(x0.x, x0.y);
        __half2 h0b = __floats2half2_rn(x0.z, x0.w);
        __half2 h1a = __floats2half2_rn(x1.x, x1.y);
        __half2 h1b = __floats2half2_rn(x1.z, x1.w);
        uint2 p0, p1;
        p0.x = *(uint32_t*)&h0a; p0.y = *(uint32_t*)&h0b;
        p1.x = *(uint32_t*)&h1a; p1.y = *(uint32_t*)&h1b;
        *(uint2*)(smem + A_OFF(b) + aStoreOff) = p0;            // panel 0
        *(uint2*)(smem + A_OFF(b) + 4096 + aStoreOff) = p1;     // panel 1
    };

    // ldmatrix address components (plane layout, conflict-free: 16B row stride)
    const uint32_t aRowOff = (uint32_t)(lane >> 4) * 2048 +
                             (uint32_t)(mh * 64 + (lane & 15)) * 16;
    const uint32_t bRowOff = (uint32_t)((lane >> 3) & 1) * 4096 +
                             (uint32_t)(ng * 32 + (lane >> 4) * 8 + (lane & 7)) * 16;

    // ---- prologue ----
    cpW(0, 0); cp_commit();
    float4 x0 = *(const float4*)(enc + rowBase + k4);
    float4 x1 = *(const float4*)(enc + rowBase + 16 + k4);

    #pragma unroll 1
    for (int i = 0; i < NIT; i++) {
        const int b = i & 1;
        stsA(b, x0, x1);
        cp_wait0();        // this thread's W(i) copies done
        __syncthreads();   // everyone's W(i) + A stores visible
        if (i + 1 < NIT) {
            x0 = *(const float4*)(enc + rowBase + (size_t)(i + 1) * 32 + k4);
            x1 = *(const float4*)(enc + rowBase + (size_t)(i + 1) * 32 + 16 + k4);
            cpW(i + 1, b ^ 1);
            cp_commit();
        }

        #pragma unroll
        for (int p = 0; p < 2; p++) {
            uint32_t aH[4][4];
            #pragma unroll
            for (int mi = 0; mi < 4; mi++)
                ldmx4(aH[mi], sb + A_OFF(b) + (uint32_t)p * 4096 + (uint32_t)mi * 256 + aRowOff);
            uint32_t bb[2][4];   // [ntp]: r0,r1 = nt even, r2,r3 = nt odd
            #pragma unroll
            for (int ntp = 0; ntp < 2; ntp++)
                ldmx4(bb[ntp], sb + W_OFF(b) + (uint32_t)p * 8192 + (uint32_t)ntp * 256 + bRowOff);
            #pragma unroll
            for (int nt = 0; nt < 4; nt++) {
                const uint32_t b0 = bb[nt >> 1][(nt & 1) * 2];
                const uint32_t b1 = bb[nt >> 1][(nt & 1) * 2 + 1];
                #pragma unroll
                for (int mi = 0; mi < 4; mi++)
                    mma16816(c[mi][nt], aH[mi], b0, b1);
            }
        }
    }

    // ---- epilogue: + dproj (exact fp32), tanh, dot v, reduce ----
    const int g = lane >> 2, t4 = lane & 3;
    float p[8];
    #pragma unroll
    for (int i = 0; i < 8; i++) p[i] = 0.f;

    #pragma unroll
    for (int nt = 0; nt < 4; nt++) {
        const int a0 = aBase + ng * 32 + nt * 8 + t4 * 2;
        const float v0 = __ldg(v + a0), v1 = __ldg(v + a0 + 1);
        #pragma unroll
        for (int mi = 0; mi < 4; mi++) {
            const int n0 = mi * 16 + g;
            float2 d0 = *(const float2*)(g_dproj + (size_t)n0 * AA + a0);
            float2 d1 = *(const float2*)(g_dproj + (size_t)(n0 + 8) * AA + a0);
            p[mi * 2 + 0] += tanh_fast(c[mi][nt][0] + d0.x) * v0 +
                             tanh_fast(c[mi][nt][1] + d0.y) * v1;
            p[mi * 2 + 1] += tanh_fast(c[mi][nt][2] + d1.x) * v0 +
                             tanh_fast(c[mi][nt][3] + d1.y) * v1;
        }
    }
    #pragma unroll
    for (int i = 0; i < 8; i++) {
        p[i] += __shfl_down_sync(0xffffffffu, p[i], 1);
        p[i] += __shfl_down_sync(0xffffffffu, p[i], 2);
    }
    float* red = (float*)(smem + RED_OFF);   // [128][8], reuses A region
    __syncthreads();
    if (t4 == 0) {
        #pragma unroll
        for (int mi = 0; mi < 4; mi++) {
            int r0 = mh * 64 + mi * 16 + g;
            red[r0 * 8 + ng] = p[mi * 2 + 0];
            red[(r0 + 8) * 8 + ng] = p[mi * 2 + 1];
        }
    }
    __syncthreads();
    if (tid < 128) {
        float s = 0.f;
        #pragma unroll
        for (int w = 0; w < 8; w++) s += red[tid * 8 + w];
        int t = tile * 2 + (tid >> 6);
        int n = tid & 63;
        g_scoresP[(size_t)half * (NN * TT) + (size_t)n * TT + t] = s;
    }
}

// ---------------------------------------------------------------------------
// softmax over T per column n — 512 threads, one float4 per thread
// ---------------------------------------------------------------------------
__global__ __launch_bounds__(512) void softmax_kernel(float* __restrict__ out_alpha) {
    const int n = blockIdx.x, tid = threadIdx.x;
    const int lane = tid & 31, w = tid >> 5;
    __shared__ float sm[16];
    const float* s0 = g_scoresP + (size_t)n * TT;
    const float* s1 = g_scoresP + (size_t)NN * TT + (size_t)n * TT;

    float4 a4 = *(const float4*)(s0 + tid * 4);
    float4 b4 = *(const float4*)(s1 + tid * 4);
    float s[4] = {a4.x + b4.x, a4.y + b4.y, a4.z + b4.z, a4.w + b4.w};

    float m = fmaxf(fmaxf(s[0], s[1]), fmaxf(s[2], s[3]));
    #pragma unroll
    for (int o = 16; o; o >>= 1) m = fmaxf(m, __shfl_xor_sync(0xffffffffu, m, o));
    if (lane == 0) sm[w] = m;
    __syncthreads();
    if (w == 0) {
        float t = sm[lane & 15];
        #pragma unroll
        for (int o = 8; o; o >>= 1) t = fmaxf(t, __shfl_xor_sync(0xffffffffu, t, o));
        sm[lane & 15] = t;
    }
    __syncthreads();
    m = sm[0];

    float e[4], acc = 0.f;
    #pragma unroll
    for (int i = 0; i < 4; i++) { e[i] = expf(s[i] - m); acc += e[i]; }
    #pragma unroll
    for (int o = 16; o; o >>= 1) acc += __shfl_xor_sync(0xffffffffu, acc, o);
    __syncthreads();
    if (lane == 0) sm[w] = acc;
    __syncthreads();
    if (w == 0) {
        float t = sm[lane & 15];
        #pragma unroll
        for (int o = 8; o; o >>= 1) t += __shfl_xor_sync(0xffffffffu, t, o);
        sm[lane & 15] = t;
    }
    __syncthreads();
    const float inv = 1.0f / sm[0];

    float4 al;
    al.x = e[0] * inv; al.y = e[1] * inv; al.z = e[2] * inv; al.w = e[3] * inv;
    *(float4*)(g_alphaT + (size_t)n * TT + tid * 4) = al;
    const int t0 = tid * 4;
    out_alpha[(size_t)(t0 + 0) * NN + n] = al.x;
    out_alpha[(size_t)(t0 + 1) * NN + n] = al.y;
    out_alpha[(size_t)(t0 + 2) * NN + n] = al.z;
    out_alpha[(size_t)(t0 + 3) * NN + n] = al.w;
}

// ---------------------------------------------------------------------------
// ctx = alpha^T * enc  (partials + reduce) — at DRAM roofline already
// ---------------------------------------------------------------------------
__global__ __launch_bounds__(256) void ctx_partial_kernel(const float* __restrict__ enc) {
    const int tc = blockIdx.x & (TCH - 1);
    const int n = blockIdx.x / TCH;
    const int e0 = threadIdx.x * 4;
    float4 acc = make_float4(0.f, 0.f, 0.f, 0.f);
    const int tBeg = tc * (TT / TCH);
    #pragma unroll 4
    for (int t = tBeg; t < tBeg + TT / TCH; ++t) {
        float al = g_alphaT[(size_t)n * TT + t];
        float4 ev = *(const float4*)(enc + ((size_t)t * NN + n) * EE + e0);
        acc.x += al * ev.x; acc.y += al * ev.y;
        acc.z += al * ev.z; acc.w += al * ev.w;
    }
    *(float4*)&g_part[((size_t)tc * NN + n) * EE + e0] = acc;
}

__global__ void ctx_reduce_kernel(float* __restrict__ out_ctx) {
    const int n = blockIdx.x;
    const int e0 = threadIdx.x * 4;
    float4 acc = make_float4(0.f, 0.f, 0.f, 0.f);
    #pragma unroll
    for (int tc = 0; tc < TCH; ++tc) {
        float4 p = *(const float4*)&g_part[((size_t)tc * NN + n) * EE + e0];
        acc.x += p.x; acc.y += p.y; acc.z += p.z; acc.w += p.w;
    }
    *(float4*)&out_ctx[(size_t)n * EE + e0] = acc;
}

// ---------------------------------------------------------------------------
extern "C" void kernel_launch(void* const* d_in, const int* in_sizes, int n_in,
                              void* d_out, int out_size) {
    const float* enc = (const float*)d_in[0];   // [T, N, E]
    const float* dec = (const float*)d_in[1];   // [N, D]
    const float* We  = (const float*)d_in[2];   // [A, E]
    const float* Wd  = (const float*)d_in[3];   // [A, D]
    const float* v   = (const float*)d_in[4];   // [1, A]

    float* out = (float*)d_out;
    float* out_ctx = out;                 // [N, E]
    float* out_alpha = out + NN * EE;     // [T, N]

    prepW_kernel<<<(AA * EE + 255) / 256, 256>>>(We);
    dproj_kernel<<<NN, 512>>>(dec, Wd);
    scores_mma_kernel<<<TT, 512, SMEMSZ>>>(enc, v);
    softmax_kernel<<<NN, 512>>>(out_alpha);
    ctx_partial_kernel<<<NN * TCH, 256>>>(enc);
    ctx_reduce_kernel<<<NN, 256>>>(out_ctx);
}